// round 2
// baseline (speedup 1.0000x reference)
#include <cuda_runtime.h>
#include <math.h>

#define NB   1024
#define NC   10
#define NPIX 900
#define NTH  256

// per-batch scratch: ce_sum, exact, copy_flag, d2, missing
__device__ float g_scr[NB * 5];

__global__ __launch_bounds__(NTH) void loss_main(
    const float* __restrict__ pred,
    const float* __restrict__ tgt,
    const float* __restrict__ inp)
{
    __shared__ float    sh_ce;
    __shared__ int      sh_cnt;   // packed: npt | nti<<10 | npi<<20
    __shared__ unsigned sh_mask;  // pred_mask | tgt_mask<<10
    if (threadIdx.x == 0) { sh_ce = 0.0f; sh_cnt = 0; sh_mask = 0u; }
    __syncthreads();

    const int b = blockIdx.x;
    const float* __restrict__ pb = pred + (size_t)b * NC * NPIX;
    const float* __restrict__ tb = tgt  + (size_t)b * NC * NPIX;
    const float* __restrict__ gb = inp  + (size_t)b * NC * NPIX;

    float    ce_acc = 0.0f;
    int      cnt    = 0;
    unsigned mask   = 0u;

    for (int p = threadIdx.x; p < NPIX; p += NTH) {
        // target argmax (first-max semantics: strict >)
        float tm = tb[p]; int ti = 0;
        #pragma unroll
        for (int c = 1; c < NC; c++) {
            float v = tb[c * NPIX + p];
            if (v > tm) { tm = v; ti = c; }
        }
        // input argmax
        float im = gb[p]; int ii = 0;
        #pragma unroll
        for (int c = 1; c < NC; c++) {
            float v = gb[c * NPIX + p];
            if (v > im) { im = v; ii = c; }
        }
        // pred: load all 10 channels into registers (static indexing only)
        float pv[NC];
        #pragma unroll
        for (int c = 0; c < NC; c++) pv[c] = pb[c * NPIX + p];

        float pm = pv[0]; int pi = 0;
        #pragma unroll
        for (int c = 1; c < NC; c++) {
            if (pv[c] > pm) { pm = pv[c]; pi = c; }
        }
        // pred value at target index via SEL chain (no dynamic indexing)
        float pt = pv[0];
        #pragma unroll
        for (int c = 1; c < NC; c++) pt = (ti == c) ? pv[c] : pt;

        float s = 0.0f;
        #pragma unroll
        for (int c = 0; c < NC; c++) s += __expf(pv[c] - pm);
        float ce = pm + __logf(s) - pt;

        int npt = (pi != ti) ? 1 : 0;
        ce_acc += ce * (npt ? 5.0f : 1.0f);
        cnt += npt + (((ti != ii) ? 1 : 0) << 10) + (((pi != ii) ? 1 : 0) << 20);
        mask |= (1u << pi) | (1u << (ti + 10));
    }

    // warp reduce (packed fields stay < 1024 per block: per-thread max 4 pixels)
    #pragma unroll
    for (int o = 16; o > 0; o >>= 1) {
        ce_acc += __shfl_down_sync(0xffffffffu, ce_acc, o);
        cnt    += __shfl_down_sync(0xffffffffu, cnt, o);
        mask   |= __shfl_down_sync(0xffffffffu, mask, o);
    }
    if ((threadIdx.x & 31) == 0) {
        atomicAdd(&sh_ce, ce_acc);
        atomicAdd(&sh_cnt, cnt);
        atomicOr(&sh_mask, mask);
    }
    __syncthreads();

    if (threadIdx.x == 0) {
        int c   = sh_cnt;
        int npt = c & 1023;
        int nti = (c >> 10) & 1023;
        int npi = (c >> 20) & 1023;
        unsigned pmask = sh_mask & 0x3FFu;
        unsigned tmask = (sh_mask >> 10) & 0x3FFu;
        float d = (float)(npi - nti) * (1.0f / 900.0f);
        g_scr[b * 5 + 0] = sh_ce;
        g_scr[b * 5 + 1] = (npt == 0) ? 1.0f : 0.0f;                 // exact match
        g_scr[b * 5 + 2] = (nti > 0 && npi == 0) ? 1.0f : 0.0f;      // should_not_copy * did_copy
        g_scr[b * 5 + 3] = d * d;                                    // (changed - tgt_changed)^2
        g_scr[b * 5 + 4] = (float)__popc(tmask & ~pmask);            // missing colors
    }
}

__global__ __launch_bounds__(NTH) void loss_final(float* __restrict__ out)
{
    __shared__ float red[8][5];
    float s0 = 0.f, s1 = 0.f, s2 = 0.f, s3 = 0.f, s4 = 0.f;
    for (int i = threadIdx.x; i < NB; i += NTH) {
        s0 += g_scr[i * 5 + 0];
        s1 += g_scr[i * 5 + 1];
        s2 += g_scr[i * 5 + 2];
        s3 += g_scr[i * 5 + 3];
        s4 += g_scr[i * 5 + 4];
    }
    #pragma unroll
    for (int o = 16; o > 0; o >>= 1) {
        s0 += __shfl_down_sync(0xffffffffu, s0, o);
        s1 += __shfl_down_sync(0xffffffffu, s1, o);
        s2 += __shfl_down_sync(0xffffffffu, s2, o);
        s3 += __shfl_down_sync(0xffffffffu, s3, o);
        s4 += __shfl_down_sync(0xffffffffu, s4, o);
    }
    int w = threadIdx.x >> 5;
    if ((threadIdx.x & 31) == 0) {
        red[w][0] = s0; red[w][1] = s1; red[w][2] = s2; red[w][3] = s3; red[w][4] = s4;
    }
    __syncthreads();
    if (threadIdx.x == 0) {
        float t0 = 0.f, t1 = 0.f, t2 = 0.f, t3 = 0.f, t4 = 0.f;
        #pragma unroll
        for (int i = 0; i < 8; i++) {
            t0 += red[i][0]; t1 += red[i][1]; t2 += red[i][2];
            t3 += red[i][3]; t4 += red[i][4];
        }
        float ce_loss    = t0 * (1.0f / ((float)NB * (float)NPIX));
        float mean_exact = t1 * (1.0f / (float)NB);
        float copy_pen   = 5.0f * t2 * (1.0f / (float)NB);
        float tdiff      = t3 * (1.0f / (float)NB);
        float color_pen  = 0.1f * t4;
        float total = ce_loss - mean_exact + copy_pen + tdiff + color_pen;
        if (isnan(total))        total = 2.0f;
        else if (total > 100.0f) total = 10.0f;
        out[0] = total;
        out[1] = ce_loss;
        out[2] = copy_pen;
        out[3] = mean_exact;   // -exact_bonus
        out[4] = t1;           // sum of exact matches
        out[5] = tdiff;
    }
}

extern "C" void kernel_launch(void* const* d_in, const int* in_sizes, int n_in,
                              void* d_out, int out_size)
{
    const float* pred   = (const float*)d_in[0];
    const float* target = (const float*)d_in[1];
    const float* inp    = (const float*)d_in[2];
    float* out = (float*)d_out;

    loss_main<<<NB, NTH>>>(pred, target, inp);
    loss_final<<<1, NTH>>>(out);
}